// round 2
// baseline (speedup 1.0000x reference)
#include <cuda_runtime.h>
#include <math.h>

#define B_   32768
#define H_   256
#define DK_  64
#define DV_  128
#define S_   8192
#define NA_  4096

// ---- static device scratch (no allocs allowed) ----
__device__ float g_qs [(size_t)B_ * DK_];   // q * invnorm / TEMP       (8 MB)
__device__ float g_knT[(size_t)DK_ * NA_];  // normalized keys, k-major (1 MB)
__device__ float g_vg [(size_t)NA_ * DV_];  // gathered values          (2 MB)
__device__ float g_colsum[NA_];
__device__ int   g_mode;                    // 1 = int64 indices, 0 = int32

__global__ void k_detect(const void* a) {
    const long long* a64 = (const long long*)a;
    long long v0 = a64[0], v1 = a64[1];
    g_mode = (v0 >= 0 && v0 < S_ && v1 >= 0 && v1 < S_) ? 1 : 0;
}
__device__ __forceinline__ int load_idx(const void* a, int i) {
    return g_mode ? (int)((const long long*)a)[i] : ((const int*)a)[i];
}

// ---- K1: query = hidden @ kw^T ; also g_qs = q*invnorm/TEMP ----
#define QPROJ_SMEM ((16384 + 16384 + 64) * 4)
__global__ __launch_bounds__(256) void k_qproj(const float* __restrict__ hidden,
                                               const float* __restrict__ kw,
                                               float* __restrict__ out_q) {
    extern __shared__ float sm1[];
    float* hid_s = sm1;          // [64][256]
    float* kwT   = sm1 + 16384;  // [256][64]
    float* inv_s = sm1 + 32768;  // [64]
    const int tid = threadIdx.x;
    const int rowbase = blockIdx.x * 64;

    #pragma unroll
    for (int i = 0; i < 16; ++i) {
        int id = tid + i * 256;
        int r = id >> 6, c4 = id & 63;
        *(float4*)&hid_s[r * 256 + c4 * 4] =
            *(const float4*)&hidden[(size_t)(rowbase + r) * 256 + c4 * 4];
    }
    #pragma unroll
    for (int i = 0; i < 16; ++i) {
        int id = tid + i * 256;
        int c = id & 63, k4 = id >> 6;
        float4 v = *(const float4*)&kw[(size_t)c * 256 + k4 * 4];
        kwT[(k4 * 4 + 0) * 64 + c] = v.x;
        kwT[(k4 * 4 + 1) * 64 + c] = v.y;
        kwT[(k4 * 4 + 2) * 64 + c] = v.z;
        kwT[(k4 * 4 + 3) * 64 + c] = v.w;
    }
    __syncthreads();

    const int tx = tid & 15, ty = tid >> 4;
    float acc[4][4] = {};
    #pragma unroll 4
    for (int k = 0; k < 256; ++k) {
        float4 b = *(float4*)&kwT[k * 64 + tx * 4];
        #pragma unroll
        for (int i = 0; i < 4; ++i) {
            float a = hid_s[(ty * 4 + i) * 256 + k];
            acc[i][0] += a * b.x; acc[i][1] += a * b.y;
            acc[i][2] += a * b.z; acc[i][3] += a * b.w;
        }
    }
    __syncthreads();
    float* q_s = hid_s;  // reuse, padded stride 68
    #pragma unroll
    for (int i = 0; i < 4; ++i)
        *(float4*)&q_s[(ty * 4 + i) * 68 + tx * 4] =
            make_float4(acc[i][0], acc[i][1], acc[i][2], acc[i][3]);
    __syncthreads();
    if (tid < 64) {
        float ss = 0.f;
        #pragma unroll
        for (int c4 = 0; c4 < 16; ++c4) {
            float4 v = *(float4*)&q_s[tid * 68 + c4 * 4];
            ss += v.x * v.x + v.y * v.y + v.z * v.z + v.w * v.w;
        }
        inv_s[tid] = 1.0f / fmaxf(sqrtf(ss), 1e-12f);
    }
    __syncthreads();
    #pragma unroll
    for (int i = 0; i < 4; ++i) {
        int r = ty * 4 + i;
        float4 v = make_float4(acc[i][0], acc[i][1], acc[i][2], acc[i][3]);
        *(float4*)&out_q[(size_t)(rowbase + r) * 64 + tx * 4] = v;
        float s = inv_s[r] * 10.0f;   // 1/TEMP folded in
        *(float4*)&g_qs[(size_t)(rowbase + r) * 64 + tx * 4] =
            make_float4(v.x * s, v.y * s, v.z * s, v.w * s);
    }
}

// ---- K2: normalize gathered keys (k-major), gather values, zero colsum ----
__global__ __launch_bounds__(64) void k_prep(const float* __restrict__ slots_key,
                                             const float* __restrict__ slots_value,
                                             const void* __restrict__ active_idx) {
    const int i = blockIdx.x, t = threadIdx.x;
    const int idx = load_idx(active_idx, i);
    float v = slots_key[(size_t)idx * DK_ + t];
    float ss = v * v;
    #pragma unroll
    for (int o = 16; o > 0; o >>= 1) ss += __shfl_down_sync(0xffffffffu, ss, o);
    __shared__ float sred[2];
    if ((t & 31) == 0) sred[t >> 5] = ss;
    __syncthreads();
    float inv = 1.0f / fmaxf(sqrtf(sred[0] + sred[1]), 1e-12f);
    g_knT[(size_t)t * NA_ + i] = v * inv;
    g_vg[(size_t)i * DV_ + t]      = slots_value[(size_t)idx * DV_ + t];
    g_vg[(size_t)i * DV_ + 64 + t] = slots_value[(size_t)idx * DV_ + 64 + t];
    if (t == 0) g_colsum[i] = 0.f;
}

// ---- K3: fused exp(sims) -> softmax -> attn + ctx + colsum ----
// 512 threads, 8 rows/CTA. smem: p[8][4096] | kbuf[32][512] (=vbuf[128][128]) | qs[64][8] | l[8]
#define ATTN_SMEM ((32768 + 16384 + 512 + 8) * 4)
__global__ __launch_bounds__(512) void k_attn(float* __restrict__ out_ctx,
                                              float* __restrict__ out_attn) {
    extern __shared__ float sm[];
    float* p    = sm;            // 32768
    float* kbuf = sm + 32768;    // 16384 (also vbuf)
    float* qs_s = sm + 49152;    // 512
    float* l_s  = sm + 49664;    // 8
    const int tid = threadIdx.x;
    const int rowbase = blockIdx.x * 8;

    if (tid < 8) l_s[tid] = 0.f;
    { int r = tid >> 6, k = tid & 63;
      qs_s[k * 8 + r] = g_qs[(size_t)(rowbase + r) * 64 + k]; }

    float sum[8];
    #pragma unroll
    for (int r = 0; r < 8; ++r) sum[r] = 0.f;

    // Phase A: sims -> exp into p
    for (int tile = 0; tile < 8; ++tile) {
        const int cb = tile * 512;
        float acc[8];
        #pragma unroll
        for (int r = 0; r < 8; ++r) acc[r] = 0.f;

        #pragma unroll
        for (int half = 0; half < 2; ++half) {
            __syncthreads();
            #pragma unroll
            for (int i = 0; i < 8; ++i) {
                int id = tid + i * 512;
                int kk = id >> 7, c4 = id & 127;
                *(float4*)&kbuf[kk * 512 + c4 * 4] =
                    *(const float4*)&g_knT[(size_t)(half * 32 + kk) * NA_ + cb + c4 * 4];
            }
            __syncthreads();
            #pragma unroll 4
            for (int kk = 0; kk < 32; ++kk) {
                float kv = kbuf[kk * 512 + tid];
                float4 a0 = *(float4*)&qs_s[(half * 32 + kk) * 8];
                float4 a1 = *(float4*)&qs_s[(half * 32 + kk) * 8 + 4];
                acc[0] += a0.x * kv; acc[1] += a0.y * kv;
                acc[2] += a0.z * kv; acc[3] += a0.w * kv;
                acc[4] += a1.x * kv; acc[5] += a1.y * kv;
                acc[6] += a1.z * kv; acc[7] += a1.w * kv;
            }
        }
        #pragma unroll
        for (int r = 0; r < 8; ++r) {
            float e = __expf(acc[r]);          // logits in [-10,10]: safe, no max pass
            p[r * 4096 + cb + tid] = e;
            sum[r] += e;
        }
    }
    __syncthreads();

    // row-sum reduction
    int lane = tid & 31;
    #pragma unroll
    for (int r = 0; r < 8; ++r) {
        float s = sum[r];
        #pragma unroll
        for (int o = 16; o > 0; o >>= 1) s += __shfl_down_sync(0xffffffffu, s, o);
        if (lane == 0) atomicAdd(&l_s[r], s);
    }
    __syncthreads();
    float invl[8];
    #pragma unroll
    for (int r = 0; r < 8; ++r) invl[r] = 1.0f / l_s[r];

    // attn write (normalized), coalesced float4
    #pragma unroll
    for (int r = 0; r < 8; ++r) {
        float iv = invl[r];
        #pragma unroll
        for (int j = 0; j < 2; ++j) {
            int c4 = tid + j * 512;
            float4 v = *(float4*)&p[r * 4096 + c4 * 4];
            v.x *= iv; v.y *= iv; v.z *= iv; v.w *= iv;
            *(float4*)&out_attn[(size_t)(rowbase + r) * 4096 + c4 * 4] = v;
        }
    }

    // colsum for usage EMA
    #pragma unroll
    for (int j = 0; j < 8; ++j) {
        int c = tid + j * 512;
        float s = 0.f;
        #pragma unroll
        for (int r = 0; r < 8; ++r) s += p[r * 4096 + c] * invl[r];
        atomicAdd(&g_colsum[c], s);
    }

    // Phase B: ctx = (p @ V) * invl ; 256 active threads, float4 over DV
    const int ty = tid >> 5, tx = tid & 31;   // row 0..7 (tid<256), dv-quad 0..31
    float4 ca = make_float4(0.f, 0.f, 0.f, 0.f);
    for (int st = 0; st < 32; ++st) {
        const int sb = st * 128;
        __syncthreads();
        #pragma unroll
        for (int i = 0; i < 8; ++i) {
            int id = tid + i * 512;
            int s = id >> 5, d4 = id & 31;
            *(float4*)&kbuf[s * 128 + d4 * 4] =
                *(const float4*)&g_vg[(size_t)(sb + s) * 128 + d4 * 4];
        }
        __syncthreads();
        if (tid < 256) {
            #pragma unroll 4
            for (int s = 0; s < 128; ++s) {
                float pv = p[ty * 4096 + sb + s];
                float4 v = *(float4*)&kbuf[s * 128 + tx * 4];
                ca.x += pv * v.x; ca.y += pv * v.y;
                ca.z += pv * v.z; ca.w += pv * v.w;
            }
        }
    }
    if (tid < 256) {
        float sc = invl[ty];
        ca.x *= sc; ca.y *= sc; ca.z *= sc; ca.w *= sc;
        *(float4*)&out_ctx[(size_t)(rowbase + ty) * 128 + tx * 4] = ca;
    }
}

// ---- K4: usage EMA ----
__global__ void k_usage_copy(const float* __restrict__ ue, float* __restrict__ out) {
    int i = blockIdx.x * 256 + threadIdx.x;
    if (i < S_) out[i] = ue[i];
}
__global__ void k_usage_scatter(const float* __restrict__ ue,
                                const void* __restrict__ aidx,
                                float* __restrict__ out) {
    int i = blockIdx.x * 256 + threadIdx.x;
    if (i < NA_) {
        int idx = load_idx(aidx, i);
        out[idx] = 0.95f * ue[idx] + 0.05f * (g_colsum[i] * (1.0f / 32768.0f));
    }
}

extern "C" void kernel_launch(void* const* d_in, const int* in_sizes, int n_in,
                              void* d_out, int out_size) {
    const float* hidden = (const float*)d_in[0];
    const float* kw     = (const float*)d_in[1];
    const float* skey   = (const float*)d_in[2];
    const float* sval   = (const float*)d_in[3];
    const float* uema   = (const float*)d_in[4];
    const void*  aidx   = d_in[5];

    float* out    = (float*)d_out;
    float* o_ctx  = out;                                  // [B,128]
    float* o_attn = out + (size_t)4194304;                // [B,4096]
    float* o_q    = out + (size_t)138412032;              // [B,64]
    float* o_use  = out + (size_t)140509184;              // [S]

    static int attr_done = 0;
    if (!attr_done) {
        cudaFuncSetAttribute(k_qproj, cudaFuncAttributeMaxDynamicSharedMemorySize, QPROJ_SMEM);
        cudaFuncSetAttribute(k_attn,  cudaFuncAttributeMaxDynamicSharedMemorySize, ATTN_SMEM);
        attr_done = 1;
    }

    k_detect<<<1, 1>>>(aidx);
    k_qproj<<<B_ / 64, 256, QPROJ_SMEM>>>(hidden, kw, o_q);
    k_prep<<<NA_, 64>>>(skey, sval, aidx);
    k_attn<<<B_ / 8, 512, ATTN_SMEM>>>(o_ctx, o_attn);
    k_usage_copy<<<(S_ + 255) / 256, 256>>>(uema, o_use);
    k_usage_scatter<<<(NA_ + 255) / 256, 256>>>(uema, aidx, o_use);
}

// round 4
// speedup vs baseline: 3.7858x; 3.7858x over previous
#include <cuda_runtime.h>
#include <cuda_bf16.h>
#include <math.h>
#include <stdint.h>

#define B_   32768
#define H_   256
#define DK_  64
#define DV_  128
#define S_   8192
#define NA_  4096

// ================= device scratch =================
__device__ float         g_qs  [(size_t)B_ * DK_];   // q * invnorm / TEMP
__device__ __nv_bfloat16 g_kh  [(size_t)NA_ * DK_];  // k-hat hi   [slot][dk]
__device__ __nv_bfloat16 g_kl  [(size_t)NA_ * DK_];  // k-hat lo
__device__ __nv_bfloat16 g_vhT [(size_t)DV_ * NA_];  // V^T hi     [dv][slot]
__device__ __nv_bfloat16 g_vlT [(size_t)DV_ * NA_];  // V^T lo
__device__ float         g_invl[B_];
__device__ float         g_colsum[NA_];
__device__ int           g_mode;

__global__ void k_detect(const void* a) {
    const long long* a64 = (const long long*)a;
    long long v0 = a64[0], v1 = a64[1];
    g_mode = (v0 >= 0 && v0 < S_ && v1 >= 0 && v1 < S_) ? 1 : 0;
}
__device__ __forceinline__ int load_idx(const void* a, int i) {
    return g_mode ? (int)((const long long*)a)[i] : ((const int*)a)[i];
}

// split f32 pair -> bf16x2 hi (ret) + bf16x2 lo (out param)
__device__ __forceinline__ uint32_t pack_split(float a, float b, uint32_t& lo) {
    __nv_bfloat16 ah = __float2bfloat16(a), bh = __float2bfloat16(b);
    __nv_bfloat162 hh; hh.x = ah; hh.y = bh;
    __nv_bfloat162 ll;
    ll.x = __float2bfloat16(a - __bfloat162float(ah));
    ll.y = __float2bfloat16(b - __bfloat162float(bh));
    lo = *(uint32_t*)&ll;
    return *(uint32_t*)&hh;
}

__device__ __forceinline__ void mma16816(float* c, const uint32_t* a,
                                         uint32_t b0, uint32_t b1) {
    asm volatile("mma.sync.aligned.m16n8k16.row.col.f32.bf16.bf16.f32 "
                 "{%0,%1,%2,%3}, {%4,%5,%6,%7}, {%8,%9}, {%0,%1,%2,%3};"
                 : "+f"(c[0]), "+f"(c[1]), "+f"(c[2]), "+f"(c[3])
                 : "r"(a[0]), "r"(a[1]), "r"(a[2]), "r"(a[3]), "r"(b0), "r"(b1));
}

// ---- K1: query = hidden @ kw^T ; g_qs = q*invnorm/TEMP ----
#define QPROJ_SMEM ((16384 + 16384 + 64) * 4)
__global__ __launch_bounds__(256) void k_qproj(const float* __restrict__ hidden,
                                               const float* __restrict__ kw,
                                               float* __restrict__ out_q) {
    extern __shared__ float sm1[];
    float* hid_s = sm1;
    float* kwT   = sm1 + 16384;
    float* inv_s = sm1 + 32768;
    const int tid = threadIdx.x;
    const int rowbase = blockIdx.x * 64;
    #pragma unroll
    for (int i = 0; i < 16; ++i) {
        int id = tid + i * 256, r = id >> 6, c4 = id & 63;
        *(float4*)&hid_s[r * 256 + c4 * 4] =
            *(const float4*)&hidden[(size_t)(rowbase + r) * 256 + c4 * 4];
    }
    #pragma unroll
    for (int i = 0; i < 16; ++i) {
        int id = tid + i * 256, c = id & 63, k4 = id >> 6;
        float4 v = *(const float4*)&kw[(size_t)c * 256 + k4 * 4];
        kwT[(k4 * 4 + 0) * 64 + c] = v.x; kwT[(k4 * 4 + 1) * 64 + c] = v.y;
        kwT[(k4 * 4 + 2) * 64 + c] = v.z; kwT[(k4 * 4 + 3) * 64 + c] = v.w;
    }
    __syncthreads();
    const int tx = tid & 15, ty = tid >> 4;
    float acc[4][4] = {};
    #pragma unroll 4
    for (int k = 0; k < 256; ++k) {
        float4 b = *(float4*)&kwT[k * 64 + tx * 4];
        #pragma unroll
        for (int i = 0; i < 4; ++i) {
            float a = hid_s[(ty * 4 + i) * 256 + k];
            acc[i][0] += a * b.x; acc[i][1] += a * b.y;
            acc[i][2] += a * b.z; acc[i][3] += a * b.w;
        }
    }
    __syncthreads();
    float* q_s = hid_s;
    #pragma unroll
    for (int i = 0; i < 4; ++i)
        *(float4*)&q_s[(ty * 4 + i) * 68 + tx * 4] =
            make_float4(acc[i][0], acc[i][1], acc[i][2], acc[i][3]);
    __syncthreads();
    if (tid < 64) {
        float ss = 0.f;
        #pragma unroll
        for (int c4 = 0; c4 < 16; ++c4) {
            float4 v = *(float4*)&q_s[tid * 68 + c4 * 4];
            ss += v.x * v.x + v.y * v.y + v.z * v.z + v.w * v.w;
        }
        inv_s[tid] = 1.0f / fmaxf(sqrtf(ss), 1e-12f);
    }
    __syncthreads();
    #pragma unroll
    for (int i = 0; i < 4; ++i) {
        int r = ty * 4 + i;
        float4 v = make_float4(acc[i][0], acc[i][1], acc[i][2], acc[i][3]);
        *(float4*)&out_q[(size_t)(rowbase + r) * 64 + tx * 4] = v;
        float s = inv_s[r] * 10.0f;
        *(float4*)&g_qs[(size_t)(rowbase + r) * 64 + tx * 4] =
            make_float4(v.x * s, v.y * s, v.z * s, v.w * s);
    }
}

// ---- K2: normalize keys (split bf16), transpose+split values ----
__global__ __launch_bounds__(64) void k_prep(const float* __restrict__ slots_key,
                                             const float* __restrict__ slots_value,
                                             const void* __restrict__ active_idx) {
    const int i = blockIdx.x, t = threadIdx.x;
    const int idx = load_idx(active_idx, i);
    float v = slots_key[(size_t)idx * DK_ + t];
    float ss = v * v;
    #pragma unroll
    for (int o = 16; o > 0; o >>= 1) ss += __shfl_down_sync(0xffffffffu, ss, o);
    __shared__ float sred[2];
    if ((t & 31) == 0) sred[t >> 5] = ss;
    __syncthreads();
    float inv = 1.0f / fmaxf(sqrtf(sred[0] + sred[1]), 1e-12f);
    float kn = v * inv;
    __nv_bfloat16 kh = __float2bfloat16(kn);
    g_kh[(size_t)i * DK_ + t] = kh;
    g_kl[(size_t)i * DK_ + t] = __float2bfloat16(kn - __bfloat162float(kh));
    #pragma unroll
    for (int h = 0; h < 2; ++h) {
        int d = t + h * 64;
        float vv = slots_value[(size_t)idx * DV_ + d];
        __nv_bfloat16 vh = __float2bfloat16(vv);
        g_vhT[(size_t)d * NA_ + i] = vh;
        g_vlT[(size_t)d * NA_ + i] = __float2bfloat16(vv - __bfloat162float(vh));
    }
    if (t == 0) g_colsum[i] = 0.f;
}

// ---- K3: HMMA fused attention ----
// smem rows padded: K 144B/row (bank-perm), V^T 272B/row
#define SKH 0
#define SKL 18432
#define SVH 36864
#define SVL 71680
#define MMA_SMEM 106496

__global__ __launch_bounds__(256, 1) void k_attn_mma(float* __restrict__ out_ctx,
                                                     float* __restrict__ out_attn) {
    extern __shared__ char smc[];
    const int tid  = threadIdx.x;
    const int wid  = tid >> 5, lane = tid & 31;
    const int g    = lane >> 2, tg = lane & 3;
    const int rowbase = blockIdx.x * 128;
    const int r0 = rowbase + wid * 16 + g;
    const int r1 = r0 + 8;

    // q fragments (persist whole kernel)
    uint32_t qh[4][4], ql[4][4];
    {
        const float* q0 = g_qs + (size_t)r0 * 64;
        const float* q1 = g_qs + (size_t)r1 * 64;
        #pragma unroll
        for (int kk = 0; kk < 4; ++kk) {
            int c = kk * 16 + tg * 2;
            float2 v00 = *(const float2*)(q0 + c);
            float2 v10 = *(const float2*)(q1 + c);
            float2 v01 = *(const float2*)(q0 + c + 8);
            float2 v11 = *(const float2*)(q1 + c + 8);
            qh[kk][0] = pack_split(v00.x, v00.y, ql[kk][0]);
            qh[kk][1] = pack_split(v10.x, v10.y, ql[kk][1]);
            qh[kk][2] = pack_split(v01.x, v01.y, ql[kk][2]);
            qh[kk][3] = pack_split(v11.x, v11.y, ql[kk][3]);
        }
    }

    float ctxa[64];
    #pragma unroll
    for (int i = 0; i < 64; ++i) ctxa[i] = 0.f;
    float rs0 = 0.f, rs1 = 0.f;

    const char* kh_l = smc + SKH + g * 144 + tg * 4;
    const char* kl_l = smc + SKL + g * 144 + tg * 4;
    const char* vh_l = smc + SVH + g * 272 + tg * 4;
    const char* vl_l = smc + SVL + g * 272 + tg * 4;

    #pragma unroll 1
    for (int t = 0; t < 32; ++t) {
        const int cb = t * 128;
        __syncthreads();
        #pragma unroll
        for (int i = 0; i < 4; ++i) {
            int id = tid + i * 256, row = id >> 3, c4 = id & 7;
            *(float4*)(smc + SKH + row * 144 + c4 * 16) =
                *(const float4*)(g_kh + (size_t)(cb + row) * 64 + c4 * 8);
            *(float4*)(smc + SKL + row * 144 + c4 * 16) =
                *(const float4*)(g_kl + (size_t)(cb + row) * 64 + c4 * 8);
        }
        #pragma unroll
        for (int i = 0; i < 8; ++i) {
            int id = tid + i * 256, row = id >> 4, c4 = id & 15;
            *(float4*)(smc + SVH + row * 272 + c4 * 16) =
                *(const float4*)(g_vhT + (size_t)row * NA_ + cb + c4 * 8);
            *(float4*)(smc + SVL + row * 272 + c4 * 16) =
                *(const float4*)(g_vlT + (size_t)row * NA_ + cb + c4 * 8);
        }
        __syncthreads();

        // sims: (qh+ql)(kh+kl), all 4 terms; exp; attn store; p frags
        uint32_t ph[8][4], pl[8][4];
        #pragma unroll
        for (int n = 0; n < 16; ++n) {
            float cc[4] = {0.f, 0.f, 0.f, 0.f};
            const char* kh_n = kh_l + n * (8 * 144);
            const char* kl_n = kl_l + n * (8 * 144);
            #pragma unroll
            for (int kk = 0; kk < 4; ++kk) {
                uint32_t bh0 = *(const uint32_t*)(kh_n + kk * 32);
                uint32_t bh1 = *(const uint32_t*)(kh_n + kk * 32 + 16);
                uint32_t bl0 = *(const uint32_t*)(kl_n + kk * 32);
                uint32_t bl1 = *(const uint32_t*)(kl_n + kk * 32 + 16);
                mma16816(cc, qh[kk], bh0, bh1);
                mma16816(cc, ql[kk], bh0, bh1);
                mma16816(cc, qh[kk], bl0, bl1);
                mma16816(cc, ql[kk], bl0, bl1);
            }
            float e0 = __expf(cc[0]), e1 = __expf(cc[1]);
            float e2 = __expf(cc[2]), e3 = __expf(cc[3]);
            rs0 += e0 + e1; rs1 += e2 + e3;
            int colb = cb + n * 8 + tg * 2;
            *(float2*)(out_attn + (size_t)r0 * 4096 + colb) = make_float2(e0, e1);
            *(float2*)(out_attn + (size_t)r1 * 4096 + colb) = make_float2(e2, e3);
            int j = n >> 1, h = (n & 1) * 2;
            ph[j][h]     = pack_split(e0, e1, pl[j][h]);
            ph[j][h + 1] = pack_split(e2, e3, pl[j][h + 1]);
        }

        // ctx: ph*vh + pl*vh + ph*vl
        #pragma unroll
        for (int n = 0; n < 16; ++n) {
            const char* vh_n = vh_l + n * (8 * 272);
            const char* vl_n = vl_l + n * (8 * 272);
            float* ca = ctxa + n * 4;
            #pragma unroll
            for (int kk = 0; kk < 8; ++kk) {
                uint32_t bh0 = *(const uint32_t*)(vh_n + kk * 32);
                uint32_t bh1 = *(const uint32_t*)(vh_n + kk * 32 + 16);
                uint32_t bl0 = *(const uint32_t*)(vl_n + kk * 32);
                uint32_t bl1 = *(const uint32_t*)(vl_n + kk * 32 + 16);
                mma16816(ca, ph[kk], bh0, bh1);
                mma16816(ca, pl[kk], bh0, bh1);
                mma16816(ca, ph[kk], bl0, bl1);
            }
        }
    }

    // rowsum reduce within quad (lanes of a quad cover disjoint cols of same rows)
    rs0 += __shfl_xor_sync(0xffffffffu, rs0, 1);
    rs0 += __shfl_xor_sync(0xffffffffu, rs0, 2);
    rs1 += __shfl_xor_sync(0xffffffffu, rs1, 1);
    rs1 += __shfl_xor_sync(0xffffffffu, rs1, 2);
    float i0 = 1.f / rs0, i1 = 1.f / rs1;
    if (tg == 0) { g_invl[r0] = i0; g_invl[r1] = i1; }
    #pragma unroll
    for (int n = 0; n < 16; ++n) {
        int colb = n * 8 + tg * 2;
        *(float2*)(out_ctx + (size_t)r0 * 128 + colb) =
            make_float2(ctxa[n * 4] * i0, ctxa[n * 4 + 1] * i0);
        *(float2*)(out_ctx + (size_t)r1 * 128 + colb) =
            make_float2(ctxa[n * 4 + 2] * i1, ctxa[n * 4 + 3] * i1);
    }
}

// ---- K4: normalize attn in place + column sums ----
__global__ __launch_bounds__(256) void k_norm(float* __restrict__ attn) {
    __shared__ float invl_s[128];
    const int tid = threadIdx.x;
    const int rb = blockIdx.x * 128;
    if (tid < 128) invl_s[tid] = g_invl[rb + tid];
    __syncthreads();
    float cs[16];
    #pragma unroll
    for (int j = 0; j < 16; ++j) cs[j] = 0.f;
    for (int r = 0; r < 128; ++r) {
        float iv = invl_s[r];
        float* row = attn + (size_t)(rb + r) * 4096;
        #pragma unroll
        for (int j = 0; j < 16; ++j) {
            int c = tid + j * 256;
            float v = row[c] * iv;
            row[c] = v;
            cs[j] += v;
        }
    }
    #pragma unroll
    for (int j = 0; j < 16; ++j) atomicAdd(&g_colsum[tid + j * 256], cs[j]);
}

// ---- K5: usage EMA ----
__global__ void k_usage_copy(const float* __restrict__ ue, float* __restrict__ out) {
    int i = blockIdx.x * 256 + threadIdx.x;
    if (i < S_) out[i] = ue[i];
}
__global__ void k_usage_scatter(const float* __restrict__ ue,
                                const void* __restrict__ aidx,
                                float* __restrict__ out) {
    int i = blockIdx.x * 256 + threadIdx.x;
    if (i < NA_) {
        int idx = load_idx(aidx, i);
        out[idx] = 0.95f * ue[idx] + 0.05f * (g_colsum[i] * (1.0f / 32768.0f));
    }
}

extern "C" void kernel_launch(void* const* d_in, const int* in_sizes, int n_in,
                              void* d_out, int out_size) {
    const float* hidden = (const float*)d_in[0];
    const float* kw     = (const float*)d_in[1];
    const float* skey   = (const float*)d_in[2];
    const float* sval   = (const float*)d_in[3];
    const float* uema   = (const float*)d_in[4];
    const void*  aidx   = d_in[5];

    float* out    = (float*)d_out;
    float* o_ctx  = out;
    float* o_attn = out + (size_t)4194304;
    float* o_q    = out + (size_t)138412032;
    float* o_use  = out + (size_t)140509184;

    cudaFuncSetAttribute(k_qproj,    cudaFuncAttributeMaxDynamicSharedMemorySize, QPROJ_SMEM);
    cudaFuncSetAttribute(k_attn_mma, cudaFuncAttributeMaxDynamicSharedMemorySize, MMA_SMEM);

    k_detect<<<1, 1>>>(aidx);
    k_qproj<<<B_ / 64, 256, QPROJ_SMEM>>>(hidden, kw, o_q);
    k_prep<<<NA_, 64>>>(skey, sval, aidx);
    k_attn_mma<<<B_ / 128, 256, MMA_SMEM>>>(o_ctx, o_attn);
    k_norm<<<B_ / 128, 256>>>(o_attn);
    k_usage_copy<<<(S_ + 255) / 256, 256>>>(uema, o_use);
    k_usage_scatter<<<(NA_ + 255) / 256, 256>>>(uema, aidx, o_use);
}

// round 5
// speedup vs baseline: 5.0787x; 1.3415x over previous
#include <cuda_runtime.h>
#include <cuda_bf16.h>
#include <math.h>
#include <stdint.h>

#define B_   32768
#define H_   256
#define DK_  64
#define DV_  128
#define S_   8192
#define NA_  4096

// ================= device scratch =================
__device__ float         g_qs  [(size_t)B_ * DK_];   // q * invnorm / TEMP
__device__ __nv_bfloat16 g_kh  [(size_t)NA_ * DK_];  // k-hat hi   [slot][dk]
__device__ __nv_bfloat16 g_kl  [(size_t)NA_ * DK_];  // k-hat lo
__device__ __nv_bfloat16 g_vhT [(size_t)DV_ * NA_];  // V^T hi     [dv][slot]
__device__ __nv_bfloat16 g_vlT [(size_t)DV_ * NA_];  // V^T lo
__device__ float         g_invl[B_];
__device__ float         g_colsum[NA_];
__device__ int           g_mode;

__global__ void k_detect(const void* a) {
    const long long* a64 = (const long long*)a;
    long long v0 = a64[0], v1 = a64[1];
    g_mode = (v0 >= 0 && v0 < S_ && v1 >= 0 && v1 < S_) ? 1 : 0;
}
__device__ __forceinline__ int load_idx(const void* a, int i) {
    return g_mode ? (int)((const long long*)a)[i] : ((const int*)a)[i];
}

// FFMA-pipe exp: valid for |x| <= ~40, rel err ~1e-7. No MUFU.
__device__ __forceinline__ float fast_exp(float x) {
    float y = x * 1.4426950408889634f;
    float t = y + 12582912.0f;                 // round to nearest int (2^23*1.5 trick)
    int   n = __float_as_int(t) - 0x4B400000;
    float f = y - (t - 12582912.0f);           // f in [-0.5, 0.5]
    float p = 1.5403530e-4f;                   // 2^f Taylor, ln2^k/k!
    p = fmaf(p, f, 1.3333558e-3f);
    p = fmaf(p, f, 9.6181291e-3f);
    p = fmaf(p, f, 5.5504109e-2f);
    p = fmaf(p, f, 2.4022651e-1f);
    p = fmaf(p, f, 6.9314718e-1f);
    p = fmaf(p, f, 1.0f);
    return p * __int_as_float((n + 127) << 23);
}

// split f32 pair -> bf16x2 hi (ret) + bf16x2 lo (out param)
__device__ __forceinline__ uint32_t pack_split(float a, float b, uint32_t& lo) {
    __nv_bfloat16 ah = __float2bfloat16(a), bh = __float2bfloat16(b);
    __nv_bfloat162 hh; hh.x = ah; hh.y = bh;
    __nv_bfloat162 ll;
    ll.x = __float2bfloat16(a - __bfloat162float(ah));
    ll.y = __float2bfloat16(b - __bfloat162float(bh));
    lo = *(uint32_t*)&ll;
    return *(uint32_t*)&hh;
}

__device__ __forceinline__ void mma16816(float* c, const uint32_t* a,
                                         uint32_t b0, uint32_t b1) {
    asm volatile("mma.sync.aligned.m16n8k16.row.col.f32.bf16.bf16.f32 "
                 "{%0,%1,%2,%3}, {%4,%5,%6,%7}, {%8,%9}, {%0,%1,%2,%3};"
                 : "+f"(c[0]), "+f"(c[1]), "+f"(c[2]), "+f"(c[3])
                 : "r"(a[0]), "r"(a[1]), "r"(a[2]), "r"(a[3]), "r"(b0), "r"(b1));
}

// ---- K1: query = hidden @ kw^T ; g_qs = q*invnorm/TEMP ----
#define QPROJ_SMEM ((16384 + 16384 + 64) * 4)
__global__ __launch_bounds__(256) void k_qproj(const float* __restrict__ hidden,
                                               const float* __restrict__ kw,
                                               float* __restrict__ out_q) {
    extern __shared__ float sm1[];
    float* hid_s = sm1;
    float* kwT   = sm1 + 16384;
    float* inv_s = sm1 + 32768;
    const int tid = threadIdx.x;
    const int rowbase = blockIdx.x * 64;
    #pragma unroll
    for (int i = 0; i < 16; ++i) {
        int id = tid + i * 256, r = id >> 6, c4 = id & 63;
        *(float4*)&hid_s[r * 256 + c4 * 4] =
            *(const float4*)&hidden[(size_t)(rowbase + r) * 256 + c4 * 4];
    }
    #pragma unroll
    for (int i = 0; i < 16; ++i) {
        int id = tid + i * 256, c = id & 63, k4 = id >> 6;
        float4 v = *(const float4*)&kw[(size_t)c * 256 + k4 * 4];
        kwT[(k4 * 4 + 0) * 64 + c] = v.x; kwT[(k4 * 4 + 1) * 64 + c] = v.y;
        kwT[(k4 * 4 + 2) * 64 + c] = v.z; kwT[(k4 * 4 + 3) * 64 + c] = v.w;
    }
    __syncthreads();
    const int tx = tid & 15, ty = tid >> 4;
    float acc[4][4] = {};
    #pragma unroll 4
    for (int k = 0; k < 256; ++k) {
        float4 b = *(float4*)&kwT[k * 64 + tx * 4];
        #pragma unroll
        for (int i = 0; i < 4; ++i) {
            float a = hid_s[(ty * 4 + i) * 256 + k];
            acc[i][0] += a * b.x; acc[i][1] += a * b.y;
            acc[i][2] += a * b.z; acc[i][3] += a * b.w;
        }
    }
    __syncthreads();
    float* q_s = hid_s;
    #pragma unroll
    for (int i = 0; i < 4; ++i)
        *(float4*)&q_s[(ty * 4 + i) * 68 + tx * 4] =
            make_float4(acc[i][0], acc[i][1], acc[i][2], acc[i][3]);
    __syncthreads();
    if (tid < 64) {
        float ss = 0.f;
        #pragma unroll
        for (int c4 = 0; c4 < 16; ++c4) {
            float4 v = *(float4*)&q_s[tid * 68 + c4 * 4];
            ss += v.x * v.x + v.y * v.y + v.z * v.z + v.w * v.w;
        }
        inv_s[tid] = 1.0f / fmaxf(sqrtf(ss), 1e-12f);
    }
    __syncthreads();
    #pragma unroll
    for (int i = 0; i < 4; ++i) {
        int r = ty * 4 + i;
        float4 v = make_float4(acc[i][0], acc[i][1], acc[i][2], acc[i][3]);
        *(float4*)&out_q[(size_t)(rowbase + r) * 64 + tx * 4] = v;
        float s = inv_s[r] * 10.0f;
        *(float4*)&g_qs[(size_t)(rowbase + r) * 64 + tx * 4] =
            make_float4(v.x * s, v.y * s, v.z * s, v.w * s);
    }
}

// ---- K2: normalize keys (split bf16), transpose+split values ----
__global__ __launch_bounds__(64) void k_prep(const float* __restrict__ slots_key,
                                             const float* __restrict__ slots_value,
                                             const void* __restrict__ active_idx) {
    const int i = blockIdx.x, t = threadIdx.x;
    const int idx = load_idx(active_idx, i);
    float v = slots_key[(size_t)idx * DK_ + t];
    float ss = v * v;
    #pragma unroll
    for (int o = 16; o > 0; o >>= 1) ss += __shfl_down_sync(0xffffffffu, ss, o);
    __shared__ float sred[2];
    if ((t & 31) == 0) sred[t >> 5] = ss;
    __syncthreads();
    float inv = 1.0f / fmaxf(sqrtf(sred[0] + sred[1]), 1e-12f);
    float kn = v * inv;
    __nv_bfloat16 kh = __float2bfloat16(kn);
    g_kh[(size_t)i * DK_ + t] = kh;
    g_kl[(size_t)i * DK_ + t] = __float2bfloat16(kn - __bfloat162float(kh));
    #pragma unroll
    for (int h = 0; h < 2; ++h) {
        int d = t + h * 64;
        float vv = slots_value[(size_t)idx * DV_ + d];
        __nv_bfloat16 vh = __float2bfloat16(vv);
        g_vhT[(size_t)d * NA_ + i] = vh;
        g_vlT[(size_t)d * NA_ + i] = __float2bfloat16(vv - __bfloat162float(vh));
    }
    if (t == 0) g_colsum[i] = 0.f;
}

// ---- K3: HMMA fused attention ----
#define SKH 0
#define SKL 18432
#define SVH 36864
#define SVL 71680
#define MMA_SMEM 106496

__global__ __launch_bounds__(256, 1) void k_attn_mma(float* __restrict__ out_ctx,
                                                     float* __restrict__ out_attn) {
    extern __shared__ char smc[];
    const int tid  = threadIdx.x;
    const int wid  = tid >> 5, lane = tid & 31;
    const int g    = lane >> 2, tg = lane & 3;
    const int rowbase = blockIdx.x * 128;
    const int r0 = rowbase + wid * 16 + g;
    const int r1 = r0 + 8;

    uint32_t qh[4][4], ql[4][4];
    {
        const float* q0 = g_qs + (size_t)r0 * 64;
        const float* q1 = g_qs + (size_t)r1 * 64;
        #pragma unroll
        for (int kk = 0; kk < 4; ++kk) {
            int c = kk * 16 + tg * 2;
            float2 v00 = *(const float2*)(q0 + c);
            float2 v10 = *(const float2*)(q1 + c);
            float2 v01 = *(const float2*)(q0 + c + 8);
            float2 v11 = *(const float2*)(q1 + c + 8);
            qh[kk][0] = pack_split(v00.x, v00.y, ql[kk][0]);
            qh[kk][1] = pack_split(v10.x, v10.y, ql[kk][1]);
            qh[kk][2] = pack_split(v01.x, v01.y, ql[kk][2]);
            qh[kk][3] = pack_split(v11.x, v11.y, ql[kk][3]);
        }
    }

    float ctxa[64];
    #pragma unroll
    for (int i = 0; i < 64; ++i) ctxa[i] = 0.f;
    float rs0 = 0.f, rs1 = 0.f;

    const char* kh_l = smc + SKH + g * 144 + tg * 4;
    const char* kl_l = smc + SKL + g * 144 + tg * 4;
    const char* vh_l = smc + SVH + g * 272 + tg * 4;
    const char* vl_l = smc + SVL + g * 272 + tg * 4;

    #pragma unroll 1
    for (int t = 0; t < 32; ++t) {
        const int cb = t * 128;
        __syncthreads();
        #pragma unroll
        for (int i = 0; i < 4; ++i) {
            int id = tid + i * 256, row = id >> 3, c4 = id & 7;
            *(float4*)(smc + SKH + row * 144 + c4 * 16) =
                *(const float4*)(g_kh + (size_t)(cb + row) * 64 + c4 * 8);
            *(float4*)(smc + SKL + row * 144 + c4 * 16) =
                *(const float4*)(g_kl + (size_t)(cb + row) * 64 + c4 * 8);
        }
        #pragma unroll
        for (int i = 0; i < 8; ++i) {
            int id = tid + i * 256, row = id >> 4, c4 = id & 15;
            *(float4*)(smc + SVH + row * 272 + c4 * 16) =
                *(const float4*)(g_vhT + (size_t)row * NA_ + cb + c4 * 8);
            *(float4*)(smc + SVL + row * 272 + c4 * 16) =
                *(const float4*)(g_vlT + (size_t)row * NA_ + cb + c4 * 8);
        }
        __syncthreads();

        // sims: qh*kh + ql*kh + qh*kl (3 terms), two accumulator chains
        uint32_t ph[8][4], pl[8][4];
        #pragma unroll
        for (int n = 0; n < 16; ++n) {
            float ccA[4] = {0.f, 0.f, 0.f, 0.f};
            float ccB[4] = {0.f, 0.f, 0.f, 0.f};
            const char* kh_n = kh_l + n * (8 * 144);
            const char* kl_n = kl_l + n * (8 * 144);
            #pragma unroll
            for (int kk = 0; kk < 4; ++kk) {
                uint32_t bh0 = *(const uint32_t*)(kh_n + kk * 32);
                uint32_t bh1 = *(const uint32_t*)(kh_n + kk * 32 + 16);
                uint32_t bl0 = *(const uint32_t*)(kl_n + kk * 32);
                uint32_t bl1 = *(const uint32_t*)(kl_n + kk * 32 + 16);
                mma16816(ccA, qh[kk], bh0, bh1);
                mma16816(ccB, ql[kk], bh0, bh1);
                mma16816(ccA, qh[kk], bl0, bl1);
            }
            float e0 = fast_exp(ccA[0] + ccB[0]);
            float e1 = fast_exp(ccA[1] + ccB[1]);
            float e2 = fast_exp(ccA[2] + ccB[2]);
            float e3 = fast_exp(ccA[3] + ccB[3]);
            rs0 += e0 + e1; rs1 += e2 + e3;
            int colb = cb + n * 8 + tg * 2;
            *(float2*)(out_attn + (size_t)r0 * 4096 + colb) = make_float2(e0, e1);
            *(float2*)(out_attn + (size_t)r1 * 4096 + colb) = make_float2(e2, e3);
            int j = n >> 1, h = (n & 1) * 2;
            ph[j][h]     = pack_split(e0, e1, pl[j][h]);
            ph[j][h + 1] = pack_split(e2, e3, pl[j][h + 1]);
        }

        // ctx: kk-outer for 16 independent accumulator chains
        #pragma unroll
        for (int kk = 0; kk < 8; ++kk) {
            const char* vh_k = vh_l + kk * 32;
            const char* vl_k = vl_l + kk * 32;
            #pragma unroll
            for (int n = 0; n < 16; ++n) {
                uint32_t bh0 = *(const uint32_t*)(vh_k + n * (8 * 272));
                uint32_t bh1 = *(const uint32_t*)(vh_k + n * (8 * 272) + 16);
                uint32_t bl0 = *(const uint32_t*)(vl_k + n * (8 * 272));
                uint32_t bl1 = *(const uint32_t*)(vl_k + n * (8 * 272) + 16);
                float* ca = ctxa + n * 4;
                mma16816(ca, ph[kk], bh0, bh1);
                mma16816(ca, pl[kk], bh0, bh1);
                mma16816(ca, ph[kk], bl0, bl1);
            }
        }
    }

    rs0 += __shfl_xor_sync(0xffffffffu, rs0, 1);
    rs0 += __shfl_xor_sync(0xffffffffu, rs0, 2);
    rs1 += __shfl_xor_sync(0xffffffffu, rs1, 1);
    rs1 += __shfl_xor_sync(0xffffffffu, rs1, 2);
    float i0 = 1.f / rs0, i1 = 1.f / rs1;
    if (tg == 0) { g_invl[r0] = i0; g_invl[r1] = i1; }
    #pragma unroll
    for (int n = 0; n < 16; ++n) {
        int colb = n * 8 + tg * 2;
        *(float2*)(out_ctx + (size_t)r0 * 128 + colb) =
            make_float2(ctxa[n * 4] * i0, ctxa[n * 4 + 1] * i0);
        *(float2*)(out_ctx + (size_t)r1 * 128 + colb) =
            make_float2(ctxa[n * 4 + 2] * i1, ctxa[n * 4 + 3] * i1);
    }
}

// ---- K4: normalize attn in place + column sums (float4 streaming) ----
__global__ __launch_bounds__(256) void k_norm(float* __restrict__ attn) {
    __shared__ float invl_s[64];
    const int tid = threadIdx.x;
    const int rb = blockIdx.x * 64;
    if (tid < 64) invl_s[tid] = g_invl[rb + tid];
    __syncthreads();
    float cs[16];
    #pragma unroll
    for (int j = 0; j < 16; ++j) cs[j] = 0.f;
    for (int r = 0; r < 64; ++r) {
        float iv = invl_s[r];
        float4* row = (float4*)(attn + (size_t)(rb + r) * 4096);
        #pragma unroll
        for (int j = 0; j < 4; ++j) {
            float4 v = row[tid + j * 256];
            v.x *= iv; v.y *= iv; v.z *= iv; v.w *= iv;
            row[tid + j * 256] = v;
            cs[j * 4 + 0] += v.x; cs[j * 4 + 1] += v.y;
            cs[j * 4 + 2] += v.z; cs[j * 4 + 3] += v.w;
        }
    }
    #pragma unroll
    for (int j = 0; j < 4; ++j) {
        int c = (tid + j * 256) * 4;
        atomicAdd(&g_colsum[c + 0], cs[j * 4 + 0]);
        atomicAdd(&g_colsum[c + 1], cs[j * 4 + 1]);
        atomicAdd(&g_colsum[c + 2], cs[j * 4 + 2]);
        atomicAdd(&g_colsum[c + 3], cs[j * 4 + 3]);
    }
}

// ---- K5: usage EMA ----
__global__ void k_usage_copy(const float* __restrict__ ue, float* __restrict__ out) {
    int i = blockIdx.x * 256 + threadIdx.x;
    if (i < S_) out[i] = ue[i];
}
__global__ void k_usage_scatter(const float* __restrict__ ue,
                                const void* __restrict__ aidx,
                                float* __restrict__ out) {
    int i = blockIdx.x * 256 + threadIdx.x;
    if (i < NA_) {
        int idx = load_idx(aidx, i);
        out[idx] = 0.95f * ue[idx] + 0.05f * (g_colsum[i] * (1.0f / 32768.0f));
    }
}

extern "C" void kernel_launch(void* const* d_in, const int* in_sizes, int n_in,
                              void* d_out, int out_size) {
    const float* hidden = (const float*)d_in[0];
    const float* kw     = (const float*)d_in[1];
    const float* skey   = (const float*)d_in[2];
    const float* sval   = (const float*)d_in[3];
    const float* uema   = (const float*)d_in[4];
    const void*  aidx   = d_in[5];

    float* out    = (float*)d_out;
    float* o_ctx  = out;
    float* o_attn = out + (size_t)4194304;
    float* o_q    = out + (size_t)138412032;
    float* o_use  = out + (size_t)140509184;

    cudaFuncSetAttribute(k_qproj,    cudaFuncAttributeMaxDynamicSharedMemorySize, QPROJ_SMEM);
    cudaFuncSetAttribute(k_attn_mma, cudaFuncAttributeMaxDynamicSharedMemorySize, MMA_SMEM);

    k_detect<<<1, 1>>>(aidx);
    k_qproj<<<B_ / 64, 256, QPROJ_SMEM>>>(hidden, kw, o_q);
    k_prep<<<NA_, 64>>>(skey, sval, aidx);
    k_attn_mma<<<B_ / 128, 256, MMA_SMEM>>>(o_ctx, o_attn);
    k_norm<<<B_ / 64, 256>>>(o_attn);
    k_usage_copy<<<(S_ + 255) / 256, 256>>>(uema, o_use);
    k_usage_scatter<<<(NA_ + 255) / 256, 256>>>(uema, aidx, o_use);
}

// round 6
// speedup vs baseline: 5.5832x; 1.0993x over previous
#include <cuda_runtime.h>
#include <cuda_fp16.h>
#include <math.h>
#include <stdint.h>

#define B_   32768
#define H_   256
#define DK_  64
#define DV_  128
#define S_   8192
#define NA_  4096

// ================= device scratch =================
__device__ float  g_qs  [(size_t)B_ * DK_];   // q * invnorm / TEMP
__device__ __half g_kh  [(size_t)NA_ * DK_];  // k-hat hi   [slot][dk]
__device__ __half g_kl  [(size_t)NA_ * DK_];  // k-hat lo residual
__device__ __half g_vhT [(size_t)DV_ * NA_];  // V^T hi     [dv][slot]
__device__ float  g_invl[B_];
__device__ float  g_colsum[NA_];
__device__ int    g_mode;

__global__ void k_detect(const void* a) {
    const long long* a64 = (const long long*)a;
    long long v0 = a64[0], v1 = a64[1];
    g_mode = (v0 >= 0 && v0 < S_ && v1 >= 0 && v1 < S_) ? 1 : 0;
}
__device__ __forceinline__ int load_idx(const void* a, int i) {
    return g_mode ? (int)((const long long*)a)[i] : ((const int*)a)[i];
}

// FFMA-pipe exp: valid for |x| <= ~40, rel err ~1e-7. No MUFU.
__device__ __forceinline__ float fast_exp(float x) {
    float y = x * 1.4426950408889634f;
    float t = y + 12582912.0f;
    int   n = __float_as_int(t) - 0x4B400000;
    float f = y - (t - 12582912.0f);
    float p = 1.5403530e-4f;
    p = fmaf(p, f, 1.3333558e-3f);
    p = fmaf(p, f, 9.6181291e-3f);
    p = fmaf(p, f, 5.5504109e-2f);
    p = fmaf(p, f, 2.4022651e-1f);
    p = fmaf(p, f, 6.9314718e-1f);
    p = fmaf(p, f, 1.0f);
    return p * __int_as_float((n + 127) << 23);
}

__device__ __forceinline__ uint32_t smem_to_u32(const void* p) {
    uint32_t a;
    asm("{ .reg .u64 t; cvta.to.shared.u64 t, %1; cvt.u32.u64 %0, t; }" : "=r"(a) : "l"(p));
    return a;
}
__device__ __forceinline__ void cp16(uint32_t smem, const void* g) {
    asm volatile("cp.async.cg.shared.global [%0], [%1], 16;" :: "r"(smem), "l"(g));
}

// split f32 pair -> fp16x2 hi (ret) + fp16x2 lo (out param)
__device__ __forceinline__ uint32_t pack_split_h(float a, float b, uint32_t& lo) {
    __half2 hh = __floats2half2_rn(a, b);
    float2 hf = __half22float2(hh);
    __half2 ll = __floats2half2_rn(a - hf.x, b - hf.y);
    lo = *(uint32_t*)&ll;
    return *(uint32_t*)&hh;
}

__device__ __forceinline__ void mma16816(float* c, const uint32_t* a,
                                         uint32_t b0, uint32_t b1) {
    asm volatile("mma.sync.aligned.m16n8k16.row.col.f32.f16.f16.f32 "
                 "{%0,%1,%2,%3}, {%4,%5,%6,%7}, {%8,%9}, {%0,%1,%2,%3};"
                 : "+f"(c[0]), "+f"(c[1]), "+f"(c[2]), "+f"(c[3])
                 : "r"(a[0]), "r"(a[1]), "r"(a[2]), "r"(a[3]), "r"(b0), "r"(b1));
}

// ---- K1: query = hidden @ kw^T ; g_qs = q*invnorm/TEMP ----
#define QPROJ_SMEM ((16384 + 16384 + 64) * 4)
__global__ __launch_bounds__(256) void k_qproj(const float* __restrict__ hidden,
                                               const float* __restrict__ kw,
                                               float* __restrict__ out_q) {
    extern __shared__ float sm1[];
    float* hid_s = sm1;
    float* kwT   = sm1 + 16384;
    float* inv_s = sm1 + 32768;
    const int tid = threadIdx.x;
    const int rowbase = blockIdx.x * 64;
    #pragma unroll
    for (int i = 0; i < 16; ++i) {
        int id = tid + i * 256, r = id >> 6, c4 = id & 63;
        *(float4*)&hid_s[r * 256 + c4 * 4] =
            *(const float4*)&hidden[(size_t)(rowbase + r) * 256 + c4 * 4];
    }
    #pragma unroll
    for (int i = 0; i < 16; ++i) {
        int id = tid + i * 256, c = id & 63, k4 = id >> 6;
        float4 v = *(const float4*)&kw[(size_t)c * 256 + k4 * 4];
        kwT[(k4 * 4 + 0) * 64 + c] = v.x; kwT[(k4 * 4 + 1) * 64 + c] = v.y;
        kwT[(k4 * 4 + 2) * 64 + c] = v.z; kwT[(k4 * 4 + 3) * 64 + c] = v.w;
    }
    __syncthreads();
    const int tx = tid & 15, ty = tid >> 4;
    float acc[4][4] = {};
    #pragma unroll 4
    for (int k = 0; k < 256; ++k) {
        float4 b = *(float4*)&kwT[k * 64 + tx * 4];
        #pragma unroll
        for (int i = 0; i < 4; ++i) {
            float a = hid_s[(ty * 4 + i) * 256 + k];
            acc[i][0] += a * b.x; acc[i][1] += a * b.y;
            acc[i][2] += a * b.z; acc[i][3] += a * b.w;
        }
    }
    __syncthreads();
    float* q_s = hid_s;
    #pragma unroll
    for (int i = 0; i < 4; ++i)
        *(float4*)&q_s[(ty * 4 + i) * 68 + tx * 4] =
            make_float4(acc[i][0], acc[i][1], acc[i][2], acc[i][3]);
    __syncthreads();
    if (tid < 64) {
        float ss = 0.f;
        #pragma unroll
        for (int c4 = 0; c4 < 16; ++c4) {
            float4 v = *(float4*)&q_s[tid * 68 + c4 * 4];
            ss += v.x * v.x + v.y * v.y + v.z * v.z + v.w * v.w;
        }
        inv_s[tid] = 1.0f / fmaxf(sqrtf(ss), 1e-12f);
    }
    __syncthreads();
    #pragma unroll
    for (int i = 0; i < 4; ++i) {
        int r = ty * 4 + i;
        float4 v = make_float4(acc[i][0], acc[i][1], acc[i][2], acc[i][3]);
        *(float4*)&out_q[(size_t)(rowbase + r) * 64 + tx * 4] = v;
        float s = inv_s[r] * 10.0f;
        *(float4*)&g_qs[(size_t)(rowbase + r) * 64 + tx * 4] =
            make_float4(v.x * s, v.y * s, v.z * s, v.w * s);
    }
}

// ---- K2: normalize keys (fp16 split), transpose values (fp16 hi) ----
__global__ __launch_bounds__(64) void k_prep(const float* __restrict__ slots_key,
                                             const float* __restrict__ slots_value,
                                             const void* __restrict__ active_idx) {
    const int i = blockIdx.x, t = threadIdx.x;
    const int idx = load_idx(active_idx, i);
    float v = slots_key[(size_t)idx * DK_ + t];
    float ss = v * v;
    #pragma unroll
    for (int o = 16; o > 0; o >>= 1) ss += __shfl_down_sync(0xffffffffu, ss, o);
    __shared__ float sred[2];
    if ((t & 31) == 0) sred[t >> 5] = ss;
    __syncthreads();
    float inv = 1.0f / fmaxf(sqrtf(sred[0] + sred[1]), 1e-12f);
    float kn = v * inv;
    __half kh = __float2half_rn(kn);
    g_kh[(size_t)i * DK_ + t] = kh;
    g_kl[(size_t)i * DK_ + t] = __float2half_rn(kn - __half2float(kh));
    #pragma unroll
    for (int h = 0; h < 2; ++h) {
        int d = t + h * 64;
        g_vhT[(size_t)d * NA_ + i] = __float2half_rn(slots_value[(size_t)idx * DV_ + d]);
    }
    if (t == 0) g_colsum[i] = 0.f;
}

// ---- K3: HMMA fused attention, cp.async double-buffered ----
// per buffer: KH 128x144B=18432 | KL 18432 | VH 128x272B=34816  => 71680
#define BUF_SZ  71680
#define KL_OFF  18432
#define VH_OFF  36864
#define MMA_SMEM (2 * BUF_SZ)

__global__ __launch_bounds__(256, 1) void k_attn_mma(float* __restrict__ out_ctx,
                                                     float* __restrict__ out_attn) {
    extern __shared__ char smc[];
    const uint32_t sbase = smem_to_u32(smc);
    const int tid  = threadIdx.x;
    const int wid  = tid >> 5, lane = tid & 31;
    const int g    = lane >> 2, tg = lane & 3;
    const int rowbase = blockIdx.x * 128;
    const int r0 = rowbase + wid * 16 + g;
    const int r1 = r0 + 8;

    uint32_t qh[4][4], ql[4][4];
    {
        const float* q0 = g_qs + (size_t)r0 * 64;
        const float* q1 = g_qs + (size_t)r1 * 64;
        #pragma unroll
        for (int kk = 0; kk < 4; ++kk) {
            int c = kk * 16 + tg * 2;
            float2 v00 = *(const float2*)(q0 + c);
            float2 v10 = *(const float2*)(q1 + c);
            float2 v01 = *(const float2*)(q0 + c + 8);
            float2 v11 = *(const float2*)(q1 + c + 8);
            qh[kk][0] = pack_split_h(v00.x, v00.y, ql[kk][0]);
            qh[kk][1] = pack_split_h(v10.x, v10.y, ql[kk][1]);
            qh[kk][2] = pack_split_h(v01.x, v01.y, ql[kk][2]);
            qh[kk][3] = pack_split_h(v11.x, v11.y, ql[kk][3]);
        }
    }

    float ctxa[64];
    #pragma unroll
    for (int i = 0; i < 64; ++i) ctxa[i] = 0.f;
    float rs0 = 0.f, rs1 = 0.f;

    // async tile loader: 16B chunks
    auto load_tile = [&](int t, int b) {
        const int cb = t * 128;
        const uint32_t bb = sbase + b * BUF_SZ;
        #pragma unroll
        for (int i = 0; i < 4; ++i) {            // KH: 1024 chunks
            int id = tid + i * 256, row = id >> 3, c = id & 7;
            cp16(bb + row * 144 + c * 16, g_kh + (size_t)(cb + row) * 64 + c * 8);
        }
        #pragma unroll
        for (int i = 0; i < 4; ++i) {            // KL
            int id = tid + i * 256, row = id >> 3, c = id & 7;
            cp16(bb + KL_OFF + row * 144 + c * 16, g_kl + (size_t)(cb + row) * 64 + c * 8);
        }
        #pragma unroll
        for (int i = 0; i < 8; ++i) {            // VH: 2048 chunks
            int id = tid + i * 256, row = id >> 4, c = id & 15;
            cp16(bb + VH_OFF + row * 272 + c * 16, g_vhT + (size_t)row * NA_ + cb + c * 8);
        }
        asm volatile("cp.async.commit_group;" ::: "memory");
    };

    load_tile(0, 0);

    #pragma unroll 1
    for (int t = 0; t < 32; ++t) {
        const int cb = t * 128;
        __syncthreads();                          // all readers of buf[(t+1)&1] done
        if (t < 31) load_tile(t + 1, (t + 1) & 1);
        if (t < 31) asm volatile("cp.async.wait_group 1;" ::: "memory");
        else        asm volatile("cp.async.wait_group 0;" ::: "memory");
        __syncthreads();

        const char* bufp = smc + (t & 1) * BUF_SZ;
        const char* kh_l = bufp + g * 144 + tg * 4;
        const char* kl_l = bufp + KL_OFF + g * 144 + tg * 4;
        const char* vh_l = bufp + VH_OFF + g * 272 + tg * 4;

        // sims: qh*kh + ql*kh + qh*kl (fp16, 3 terms)
        uint32_t ph[8][4], pl[8][4];
        #pragma unroll
        for (int n = 0; n < 16; ++n) {
            float ccA[4] = {0.f, 0.f, 0.f, 0.f};
            float ccB[4] = {0.f, 0.f, 0.f, 0.f};
            const char* kh_n = kh_l + n * (8 * 144);
            const char* kl_n = kl_l + n * (8 * 144);
            #pragma unroll
            for (int kk = 0; kk < 4; ++kk) {
                uint32_t bh0 = *(const uint32_t*)(kh_n + kk * 32);
                uint32_t bh1 = *(const uint32_t*)(kh_n + kk * 32 + 16);
                uint32_t bl0 = *(const uint32_t*)(kl_n + kk * 32);
                uint32_t bl1 = *(const uint32_t*)(kl_n + kk * 32 + 16);
                mma16816(ccA, qh[kk], bh0, bh1);
                mma16816(ccB, ql[kk], bh0, bh1);
                mma16816(ccA, qh[kk], bl0, bl1);
            }
            float e0 = fast_exp(ccA[0] + ccB[0]);
            float e1 = fast_exp(ccA[1] + ccB[1]);
            float e2 = fast_exp(ccA[2] + ccB[2]);
            float e3 = fast_exp(ccA[3] + ccB[3]);
            rs0 += e0 + e1; rs1 += e2 + e3;
            int colb = cb + n * 8 + tg * 2;
            *(float2*)(out_attn + (size_t)r0 * 4096 + colb) = make_float2(e0, e1);
            *(float2*)(out_attn + (size_t)r1 * 4096 + colb) = make_float2(e2, e3);
            int j = n >> 1, h = (n & 1) * 2;
            ph[j][h]     = pack_split_h(e0, e1, pl[j][h]);
            ph[j][h + 1] = pack_split_h(e2, e3, pl[j][h + 1]);
        }

        // ctx: (ph + pl) * vh (fp16, 2 terms), kk-outer for ILP
        #pragma unroll
        for (int kk = 0; kk < 8; ++kk) {
            const char* vh_k = vh_l + kk * 32;
            #pragma unroll
            for (int n = 0; n < 16; ++n) {
                uint32_t bh0 = *(const uint32_t*)(vh_k + n * (8 * 272));
                uint32_t bh1 = *(const uint32_t*)(vh_k + n * (8 * 272) + 16);
                float* ca = ctxa + n * 4;
                mma16816(ca, ph[kk], bh0, bh1);
                mma16816(ca, pl[kk], bh0, bh1);
            }
        }
    }

    rs0 += __shfl_xor_sync(0xffffffffu, rs0, 1);
    rs0 += __shfl_xor_sync(0xffffffffu, rs0, 2);
    rs1 += __shfl_xor_sync(0xffffffffu, rs1, 1);
    rs1 += __shfl_xor_sync(0xffffffffu, rs1, 2);
    float i0 = 1.f / rs0, i1 = 1.f / rs1;
    if (tg == 0) { g_invl[r0] = i0; g_invl[r1] = i1; }
    #pragma unroll
    for (int n = 0; n < 16; ++n) {
        int colb = n * 8 + tg * 2;
        *(float2*)(out_ctx + (size_t)r0 * 128 + colb) =
            make_float2(ctxa[n * 4] * i0, ctxa[n * 4 + 1] * i0);
        *(float2*)(out_ctx + (size_t)r1 * 128 + colb) =
            make_float2(ctxa[n * 4 + 2] * i1, ctxa[n * 4 + 3] * i1);
    }
}

// ---- K4: normalize attn in place + column sums (float4 streaming) ----
__global__ __launch_bounds__(256) void k_norm(float* __restrict__ attn) {
    __shared__ float invl_s[64];
    const int tid = threadIdx.x;
    const int rb = blockIdx.x * 64;
    if (tid < 64) invl_s[tid] = g_invl[rb + tid];
    __syncthreads();
    float cs[16];
    #pragma unroll
    for (int j = 0; j < 16; ++j) cs[j] = 0.f;
    for (int r = 0; r < 64; ++r) {
        float iv = invl_s[r];
        float4* row = (float4*)(attn + (size_t)(rb + r) * 4096);
        #pragma unroll
        for (int j = 0; j < 4; ++j) {
            float4 v = row[tid + j * 256];
            v.x *= iv; v.y *= iv; v.z *= iv; v.w *= iv;
            row[tid + j * 256] = v;
            cs[j * 4 + 0] += v.x; cs[j * 4 + 1] += v.y;
            cs[j * 4 + 2] += v.z; cs[j * 4 + 3] += v.w;
        }
    }
    #pragma unroll
    for (int j = 0; j < 4; ++j) {
        int c = (tid + j * 256) * 4;
        atomicAdd(&g_colsum[c + 0], cs[j * 4 + 0]);
        atomicAdd(&g_colsum[c + 1], cs[j * 4 + 1]);
        atomicAdd(&g_colsum[c + 2], cs[j * 4 + 2]);
        atomicAdd(&g_colsum[c + 3], cs[j * 4 + 3]);
    }
}

// ---- K5: usage EMA ----
__global__ void k_usage_copy(const float* __restrict__ ue, float* __restrict__ out) {
    int i = blockIdx.x * 256 + threadIdx.x;
    if (i < S_) out[i] = ue[i];
}
__global__ void k_usage_scatter(const float* __restrict__ ue,
                                const void* __restrict__ aidx,
                                float* __restrict__ out) {
    int i = blockIdx.x * 256 + threadIdx.x;
    if (i < NA_) {
        int idx = load_idx(aidx, i);
        out[idx] = 0.95f * ue[idx] + 0.05f * (g_colsum[i] * (1.0f / 32768.0f));
    }
}

extern "C" void kernel_launch(void* const* d_in, const int* in_sizes, int n_in,
                              void* d_out, int out_size) {
    const float* hidden = (const float*)d_in[0];
    const float* kw     = (const float*)d_in[1];
    const float* skey   = (const float*)d_in[2];
    const float* sval   = (const float*)d_in[3];
    const float* uema   = (const float*)d_in[4];
    const void*  aidx   = d_in[5];

    float* out    = (float*)d_out;
    float* o_ctx  = out;
    float* o_attn = out + (size_t)4194304;
    float* o_q    = out + (size_t)138412032;
    float* o_use  = out + (size_t)140509184;

    cudaFuncSetAttribute(k_qproj,    cudaFuncAttributeMaxDynamicSharedMemorySize, QPROJ_SMEM);
    cudaFuncSetAttribute(k_attn_mma, cudaFuncAttributeMaxDynamicSharedMemorySize, MMA_SMEM);

    k_detect<<<1, 1>>>(aidx);
    k_qproj<<<B_ / 64, 256, QPROJ_SMEM>>>(hidden, kw, o_q);
    k_prep<<<NA_, 64>>>(skey, sval, aidx);
    k_attn_mma<<<B_ / 128, 256, MMA_SMEM>>>(o_ctx, o_attn);
    k_norm<<<B_ / 64, 256>>>(o_attn);
    k_usage_copy<<<(S_ + 255) / 256, 256>>>(uema, o_use);
    k_usage_scatter<<<(NA_ + 255) / 256, 256>>>(uema, aidx, o_use);
}

// round 7
// speedup vs baseline: 6.6900x; 1.1982x over previous
#include <cuda_runtime.h>
#include <cuda_fp16.h>
#include <math.h>
#include <stdint.h>

#define B_   32768
#define H_   256
#define DK_  64
#define DV_  128
#define S_   8192
#define NA_  4096

// ================= device scratch =================
__device__ float  g_qs  [(size_t)B_ * DK_];   // q * invnorm / TEMP
__device__ __half g_kh  [(size_t)NA_ * DK_];  // k-hat hi   [slot][dk]
__device__ __half g_kl  [(size_t)NA_ * DK_];  // k-hat lo residual
__device__ __half g_vhT [(size_t)DV_ * NA_];  // V^T        [dv][slot]
__device__ float  g_invl[B_];
__device__ float  g_colsum[NA_];
__device__ int    g_mode;

__global__ void k_detect(const void* a) {
    const long long* a64 = (const long long*)a;
    long long v0 = a64[0], v1 = a64[1];
    g_mode = (v0 >= 0 && v0 < S_ && v1 >= 0 && v1 < S_) ? 1 : 0;
}
__device__ __forceinline__ int load_idx(const void* a, int i) {
    return g_mode ? (int)((const long long*)a)[i] : ((const int*)a)[i];
}

// FFMA-pipe exp: valid for |x| <= ~40, rel err ~1e-7. No MUFU.
__device__ __forceinline__ float fast_exp(float x) {
    float y = x * 1.4426950408889634f;
    float t = y + 12582912.0f;
    int   n = __float_as_int(t) - 0x4B400000;
    float f = y - (t - 12582912.0f);
    float p = 1.5403530e-4f;
    p = fmaf(p, f, 1.3333558e-3f);
    p = fmaf(p, f, 9.6181291e-3f);
    p = fmaf(p, f, 5.5504109e-2f);
    p = fmaf(p, f, 2.4022651e-1f);
    p = fmaf(p, f, 6.9314718e-1f);
    p = fmaf(p, f, 1.0f);
    return p * __int_as_float((n + 127) << 23);
}

__device__ __forceinline__ uint32_t smem_to_u32(const void* p) {
    uint32_t a;
    asm("{ .reg .u64 t; cvta.to.shared.u64 t, %1; cvt.u32.u64 %0, t; }" : "=r"(a) : "l"(p));
    return a;
}
__device__ __forceinline__ void cp16(uint32_t smem, const void* g) {
    asm volatile("cp.async.cg.shared.global [%0], [%1], 16;" :: "r"(smem), "l"(g));
}

// split f32 pair -> fp16x2 hi (ret) + fp16x2 lo (out param)
__device__ __forceinline__ uint32_t pack_split_h(float a, float b, uint32_t& lo) {
    __half2 hh = __floats2half2_rn(a, b);
    float2 hf = __half22float2(hh);
    __half2 ll = __floats2half2_rn(a - hf.x, b - hf.y);
    lo = *(uint32_t*)&ll;
    return *(uint32_t*)&hh;
}
__device__ __forceinline__ uint32_t pack_h(float a, float b) {
    __half2 hh = __floats2half2_rn(a, b);
    return *(uint32_t*)&hh;
}

__device__ __forceinline__ void mma16816(float* c, const uint32_t* a,
                                         uint32_t b0, uint32_t b1) {
    asm volatile("mma.sync.aligned.m16n8k16.row.col.f32.f16.f16.f32 "
                 "{%0,%1,%2,%3}, {%4,%5,%6,%7}, {%8,%9}, {%0,%1,%2,%3};"
                 : "+f"(c[0]), "+f"(c[1]), "+f"(c[2]), "+f"(c[3])
                 : "r"(a[0]), "r"(a[1]), "r"(a[2]), "r"(a[3]), "r"(b0), "r"(b1));
}

// ---- K1: query = hidden @ kw^T ; g_qs = q*invnorm/TEMP ----
#define QPROJ_SMEM ((16384 + 16384 + 64) * 4)
__global__ __launch_bounds__(256) void k_qproj(const float* __restrict__ hidden,
                                               const float* __restrict__ kw,
                                               float* __restrict__ out_q) {
    extern __shared__ float sm1[];
    float* hid_s = sm1;
    float* kwT   = sm1 + 16384;
    float* inv_s = sm1 + 32768;
    const int tid = threadIdx.x;
    const int rowbase = blockIdx.x * 64;
    #pragma unroll
    for (int i = 0; i < 16; ++i) {
        int id = tid + i * 256, r = id >> 6, c4 = id & 63;
        *(float4*)&hid_s[r * 256 + c4 * 4] =
            *(const float4*)&hidden[(size_t)(rowbase + r) * 256 + c4 * 4];
    }
    #pragma unroll
    for (int i = 0; i < 16; ++i) {
        int id = tid + i * 256, c = id & 63, k4 = id >> 6;
        float4 v = *(const float4*)&kw[(size_t)c * 256 + k4 * 4];
        kwT[(k4 * 4 + 0) * 64 + c] = v.x; kwT[(k4 * 4 + 1) * 64 + c] = v.y;
        kwT[(k4 * 4 + 2) * 64 + c] = v.z; kwT[(k4 * 4 + 3) * 64 + c] = v.w;
    }
    __syncthreads();
    const int tx = tid & 15, ty = tid >> 4;
    float acc[4][4] = {};
    #pragma unroll 4
    for (int k = 0; k < 256; ++k) {
        float4 b = *(float4*)&kwT[k * 64 + tx * 4];
        #pragma unroll
        for (int i = 0; i < 4; ++i) {
            float a = hid_s[(ty * 4 + i) * 256 + k];
            acc[i][0] += a * b.x; acc[i][1] += a * b.y;
            acc[i][2] += a * b.z; acc[i][3] += a * b.w;
        }
    }
    __syncthreads();
    float* q_s = hid_s;
    #pragma unroll
    for (int i = 0; i < 4; ++i)
        *(float4*)&q_s[(ty * 4 + i) * 68 + tx * 4] =
            make_float4(acc[i][0], acc[i][1], acc[i][2], acc[i][3]);
    __syncthreads();
    if (tid < 64) {
        float ss = 0.f;
        #pragma unroll
        for (int c4 = 0; c4 < 16; ++c4) {
            float4 v = *(float4*)&q_s[tid * 68 + c4 * 4];
            ss += v.x * v.x + v.y * v.y + v.z * v.z + v.w * v.w;
        }
        inv_s[tid] = 1.0f / fmaxf(sqrtf(ss), 1e-12f);
    }
    __syncthreads();
    #pragma unroll
    for (int i = 0; i < 4; ++i) {
        int r = ty * 4 + i;
        float4 v = make_float4(acc[i][0], acc[i][1], acc[i][2], acc[i][3]);
        *(float4*)&out_q[(size_t)(rowbase + r) * 64 + tx * 4] = v;
        float s = inv_s[r] * 10.0f;
        *(float4*)&g_qs[(size_t)(rowbase + r) * 64 + tx * 4] =
            make_float4(v.x * s, v.y * s, v.z * s, v.w * s);
    }
}

// ---- K2: normalize keys (fp16 split), transpose values (fp16) ----
__global__ __launch_bounds__(64) void k_prep(const float* __restrict__ slots_key,
                                             const float* __restrict__ slots_value,
                                             const void* __restrict__ active_idx) {
    const int i = blockIdx.x, t = threadIdx.x;
    const int idx = load_idx(active_idx, i);
    float v = slots_key[(size_t)idx * DK_ + t];
    float ss = v * v;
    #pragma unroll
    for (int o = 16; o > 0; o >>= 1) ss += __shfl_down_sync(0xffffffffu, ss, o);
    __shared__ float sred[2];
    if ((t & 31) == 0) sred[t >> 5] = ss;
    __syncthreads();
    float inv = 1.0f / fmaxf(sqrtf(sred[0] + sred[1]), 1e-12f);
    float kn = v * inv;
    __half kh = __float2half_rn(kn);
    g_kh[(size_t)i * DK_ + t] = kh;
    g_kl[(size_t)i * DK_ + t] = __float2half_rn(kn - __half2float(kh));
    #pragma unroll
    for (int h = 0; h < 2; ++h) {
        int d = t + h * 64;
        g_vhT[(size_t)d * NA_ + i] = __float2half_rn(slots_value[(size_t)idx * DV_ + d]);
    }
    if (t == 0) g_colsum[i] = 0.f;
}

// ---- K3: HMMA fused attention, cp.async double-buffered ----
// per buffer: KH 128x144B=18432 | KL 18432 | VH 128x272B=34816  => 71680
#define BUF_SZ  71680
#define KL_OFF  18432
#define VH_OFF  36864
#define MMA_SMEM (2 * BUF_SZ)

__global__ __launch_bounds__(256, 1) void k_attn_mma(float* __restrict__ out_ctx,
                                                     float* __restrict__ out_attn) {
    extern __shared__ char smc[];
    const uint32_t sbase = smem_to_u32(smc);
    const int tid  = threadIdx.x;
    const int wid  = tid >> 5, lane = tid & 31;
    const int g    = lane >> 2, tg = lane & 3;
    const int rowbase = blockIdx.x * 128;
    const int r0 = rowbase + wid * 16 + g;
    const int r1 = r0 + 8;

    uint32_t qh[4][4], ql[4][4];
    {
        const float* q0 = g_qs + (size_t)r0 * 64;
        const float* q1 = g_qs + (size_t)r1 * 64;
        #pragma unroll
        for (int kk = 0; kk < 4; ++kk) {
            int c = kk * 16 + tg * 2;
            float2 v00 = *(const float2*)(q0 + c);
            float2 v10 = *(const float2*)(q1 + c);
            float2 v01 = *(const float2*)(q0 + c + 8);
            float2 v11 = *(const float2*)(q1 + c + 8);
            qh[kk][0] = pack_split_h(v00.x, v00.y, ql[kk][0]);
            qh[kk][1] = pack_split_h(v10.x, v10.y, ql[kk][1]);
            qh[kk][2] = pack_split_h(v01.x, v01.y, ql[kk][2]);
            qh[kk][3] = pack_split_h(v11.x, v11.y, ql[kk][3]);
        }
    }

    float ctxa[64];
    #pragma unroll
    for (int i = 0; i < 64; ++i) ctxa[i] = 0.f;
    float rs0 = 0.f, rs1 = 0.f;

    auto load_tile = [&](int t, int b) {
        const int cb = t * 128;
        const uint32_t bb = sbase + b * BUF_SZ;
        #pragma unroll
        for (int i = 0; i < 4; ++i) {
            int id = tid + i * 256, row = id >> 3, c = id & 7;
            cp16(bb + row * 144 + c * 16, g_kh + (size_t)(cb + row) * 64 + c * 8);
        }
        #pragma unroll
        for (int i = 0; i < 4; ++i) {
            int id = tid + i * 256, row = id >> 3, c = id & 7;
            cp16(bb + KL_OFF + row * 144 + c * 16, g_kl + (size_t)(cb + row) * 64 + c * 8);
        }
        #pragma unroll
        for (int i = 0; i < 8; ++i) {
            int id = tid + i * 256, row = id >> 4, c = id & 15;
            cp16(bb + VH_OFF + row * 272 + c * 16, g_vhT + (size_t)row * NA_ + cb + c * 8);
        }
        asm volatile("cp.async.commit_group;" ::: "memory");
    };

    load_tile(0, 0);

    #pragma unroll 1
    for (int t = 0; t < 32; ++t) {
        const int cb = t * 128;
        __syncthreads();
        if (t < 31) load_tile(t + 1, (t + 1) & 1);
        if (t < 31) asm volatile("cp.async.wait_group 1;" ::: "memory");
        else        asm volatile("cp.async.wait_group 0;" ::: "memory");
        __syncthreads();

        const char* bufp = smc + (t & 1) * BUF_SZ;
        const char* kh_l = bufp + g * 144 + tg * 4;
        const char* kl_l = bufp + KL_OFF + g * 144 + tg * 4;
        const char* vh_l = bufp + VH_OFF + g * 272 + tg * 4;

        // sims: qh*kh + ql*kh + qh*kl, 3 independent 4-MMA chains
        uint32_t ph[8][4];
        #pragma unroll
        for (int n = 0; n < 16; ++n) {
            float ccA[4] = {0.f, 0.f, 0.f, 0.f};
            float ccB[4] = {0.f, 0.f, 0.f, 0.f};
            float ccC[4] = {0.f, 0.f, 0.f, 0.f};
            const char* kh_n = kh_l + n * (8 * 144);
            const char* kl_n = kl_l + n * (8 * 144);
            #pragma unroll
            for (int kk = 0; kk < 4; ++kk) {
                uint32_t bh0 = *(const uint32_t*)(kh_n + kk * 32);
                uint32_t bh1 = *(const uint32_t*)(kh_n + kk * 32 + 16);
                uint32_t bl0 = *(const uint32_t*)(kl_n + kk * 32);
                uint32_t bl1 = *(const uint32_t*)(kl_n + kk * 32 + 16);
                mma16816(ccA, qh[kk], bh0, bh1);
                mma16816(ccB, ql[kk], bh0, bh1);
                mma16816(ccC, qh[kk], bl0, bl1);
            }
            float e0 = fast_exp(ccA[0] + ccB[0] + ccC[0]);
            float e1 = fast_exp(ccA[1] + ccB[1] + ccC[1]);
            float e2 = fast_exp(ccA[2] + ccB[2] + ccC[2]);
            float e3 = fast_exp(ccA[3] + ccB[3] + ccC[3]);
            rs0 += e0 + e1; rs1 += e2 + e3;
            int colb = cb + n * 8 + tg * 2;
            *(float2*)(out_attn + (size_t)r0 * 4096 + colb) = make_float2(e0, e1);
            *(float2*)(out_attn + (size_t)r1 * 4096 + colb) = make_float2(e2, e3);
            int j = n >> 1, h = (n & 1) * 2;
            ph[j][h]     = pack_h(e0, e1);
            ph[j][h + 1] = pack_h(e2, e3);
        }

        // ctx: ph * vh (single term), kk-outer for 16 independent chains
        #pragma unroll
        for (int kk = 0; kk < 8; ++kk) {
            const char* vh_k = vh_l + kk * 32;
            #pragma unroll
            for (int n = 0; n < 16; ++n) {
                uint32_t bh0 = *(const uint32_t*)(vh_k + n * (8 * 272));
                uint32_t bh1 = *(const uint32_t*)(vh_k + n * (8 * 272) + 16);
                mma16816(ctxa + n * 4, ph[kk], bh0, bh1);
            }
        }
    }

    rs0 += __shfl_xor_sync(0xffffffffu, rs0, 1);
    rs0 += __shfl_xor_sync(0xffffffffu, rs0, 2);
    rs1 += __shfl_xor_sync(0xffffffffu, rs1, 1);
    rs1 += __shfl_xor_sync(0xffffffffu, rs1, 2);
    float i0 = 1.f / rs0, i1 = 1.f / rs1;
    if (tg == 0) { g_invl[r0] = i0; g_invl[r1] = i1; }
    #pragma unroll
    for (int n = 0; n < 16; ++n) {
        int colb = n * 8 + tg * 2;
        *(float2*)(out_ctx + (size_t)r0 * 128 + colb) =
            make_float2(ctxa[n * 4] * i0, ctxa[n * 4 + 1] * i0);
        *(float2*)(out_ctx + (size_t)r1 * 128 + colb) =
            make_float2(ctxa[n * 4 + 2] * i1, ctxa[n * 4 + 3] * i1);
    }
}

// ---- K4: normalize attn in place + column sums (float4 streaming) ----
__global__ __launch_bounds__(256) void k_norm(float* __restrict__ attn) {
    __shared__ float invl_s[64];
    const int tid = threadIdx.x;
    const int rb = blockIdx.x * 64;
    if (tid < 64) invl_s[tid] = g_invl[rb + tid];
    __syncthreads();
    float cs[16];
    #pragma unroll
    for (int j = 0; j < 16; ++j) cs[j] = 0.f;
    for (int r = 0; r < 64; ++r) {
        float iv = invl_s[r];
        float4* row = (float4*)(attn + (size_t)(rb + r) * 4096);
        #pragma unroll
        for (int j = 0; j < 4; ++j) {
            float4 v = row[tid + j * 256];
            v.x *= iv; v.y *= iv; v.z *= iv; v.w *= iv;
            row[tid + j * 256] = v;
            cs[j * 4 + 0] += v.x; cs[j * 4 + 1] += v.y;
            cs[j * 4 + 2] += v.z; cs[j * 4 + 3] += v.w;
        }
    }
    #pragma unroll
    for (int j = 0; j < 4; ++j) {
        int c = (tid + j * 256) * 4;
        atomicAdd(&g_colsum[c + 0], cs[j * 4 + 0]);
        atomicAdd(&g_colsum[c + 1], cs[j * 4 + 1]);
        atomicAdd(&g_colsum[c + 2], cs[j * 4 + 2]);
        atomicAdd(&g_colsum[c + 3], cs[j * 4 + 3]);
    }
}

// ---- K5: usage EMA ----
__global__ void k_usage_copy(const float* __restrict__ ue, float* __restrict__ out) {
    int i = blockIdx.x * 256 + threadIdx.x;
    if (i < S_) out[i] = ue[i];
}
__global__ void k_usage_scatter(const float* __restrict__ ue,
                                const void* __restrict__ aidx,
                                float* __restrict__ out) {
    int i = blockIdx.x * 256 + threadIdx.x;
    if (i < NA_) {
        int idx = load_idx(aidx, i);
        out[idx] = 0.95f * ue[idx] + 0.05f * (g_colsum[i] * (1.0f / 32768.0f));
    }
}

extern "C" void kernel_launch(void* const* d_in, const int* in_sizes, int n_in,
                              void* d_out, int out_size) {
    const float* hidden = (const float*)d_in[0];
    const float* kw     = (const float*)d_in[1];
    const float* skey   = (const float*)d_in[2];
    const float* sval   = (const float*)d_in[3];
    const float* uema   = (const float*)d_in[4];
    const void*  aidx   = d_in[5];

    float* out    = (float*)d_out;
    float* o_ctx  = out;
    float* o_attn = out + (size_t)4194304;
    float* o_q    = out + (size_t)138412032;
    float* o_use  = out + (size_t)140509184;

    cudaFuncSetAttribute(k_qproj,    cudaFuncAttributeMaxDynamicSharedMemorySize, QPROJ_SMEM);
    cudaFuncSetAttribute(k_attn_mma, cudaFuncAttributeMaxDynamicSharedMemorySize, MMA_SMEM);

    k_detect<<<1, 1>>>(aidx);
    k_qproj<<<B_ / 64, 256, QPROJ_SMEM>>>(hidden, kw, o_q);
    k_prep<<<NA_, 64>>>(skey, sval, aidx);
    k_attn_mma<<<B_ / 128, 256, MMA_SMEM>>>(o_ctx, o_attn);
    k_norm<<<B_ / 64, 256>>>(o_attn);
    k_usage_copy<<<(S_ + 255) / 256, 256>>>(uema, o_use);
    k_usage_scatter<<<(NA_ + 255) / 256, 256>>>(uema, aidx, o_use);
}